// round 6
// baseline (speedup 1.0000x reference)
#include <cuda_runtime.h>

// Problem constants
#define TD     64
#define MODES  16
#define MRI    32          // 2*MODES
#define CIN    64
#define COUT   64
#define PD     16384       // N*D
#define SCOL   1048576     // PD*64 floats per time row
#define TILE_P 8
#define NBLK   (PD / TILE_P)   // 2048 CTAs
#define NTHR   512

#define TWO_PI_OVER_64 0.09817477042468103870f

typedef unsigned long long u64;

// Packed, transposed weights: g_W[m][c2][o] = ( (WR[2c2],WR[2c2+1]), (WI[2c2],WI[2c2+1]) )
__device__ ulonglong2 g_W[MODES * 32 * 64];   // 512 KB

// ---------- packed f32x2 helpers ----------
__device__ __forceinline__ u64 pack2(float a, float b) {
    u64 r;
    asm("mov.b64 %0, {%1, %2};" : "=l"(r) : "f"(a), "f"(b));
    return r;
}
__device__ __forceinline__ void unpack2(u64 v, float &lo, float &hi) {
    asm("mov.b64 {%0, %1}, %2;" : "=f"(lo), "=f"(hi) : "l"(v));
}
__device__ __forceinline__ void fma2(u64 &d, u64 a, u64 b) {
    asm("fma.rn.f32x2 %0, %1, %2, %0;" : "+l"(d) : "l"(a), "l"(b));
}
__device__ __forceinline__ u64 add2(u64 a, u64 b) {
    u64 r;
    asm("add.rn.f32x2 %0, %1, %2;" : "=l"(r) : "l"(a), "l"(b));
    return r;
}
__device__ __forceinline__ float hadd(u64 v) {
    float lo, hi;
    unpack2(v, lo, hi);
    return lo + hi;
}

// =====================================================================
// One-time weight repack: w[c][o][m][2]  ->  g_W[m][c2][o]
// =====================================================================
__global__ void __launch_bounds__(256) w_pack(const float* __restrict__ w) {
    int idx = blockIdx.x * 256 + threadIdx.x;     // 0 .. 32767
    int m  = idx >> 11;
    int c2 = (idx >> 6) & 31;
    int o  = idx & 63;
    int c0 = 2 * c2;
    const float* b0 = w + ((((c0    ) * 64 + o) * MODES + m) << 1);
    const float* b1 = w + ((((c0 + 1) * 64 + o) * MODES + m) << 1);
    ulonglong2 v;
    v.x = pack2(b0[0], b1[0]);
    v.y = pack2(b0[1], b1[1]);
    g_W[idx] = v;
}

// =====================================================================
// Fused spectral conv. 512 threads, 8 pixels per CTA, 224 KB smem.
// smem layout (bytes):
//   [0      , 16384 ) F2  [mri][t]   packed (f,f)
//   [16384  , 32768 ) G2  [t][mri]   packed (g,g)
//   [32768  , 98304 ) Xft [mri][8p][64c] f32   (64 KB)
//   [98304  ,163840 ) Y   [mri][8p][64o] f32   (64 KB)
//   [163840 ,196608 ) W buf 0  [c2][o] ulonglong2
//   [196608 ,229376 ) W buf 1
// =====================================================================
__global__ void __launch_bounds__(NTHR, 1) fused_spectral(const float* __restrict__ x,
                                                          float* __restrict__ out) {
    extern __shared__ __align__(16) char smem[];
    u64*        F2  = reinterpret_cast<u64*>(smem);
    u64*        G2  = reinterpret_cast<u64*>(smem + 16384);
    float*      Xsm = reinterpret_cast<float*>(smem + 32768);
    float*      Ysm = reinterpret_cast<float*>(smem + 98304);
    ulonglong2* Wb0 = reinterpret_cast<ulonglong2*>(smem + 163840);
    ulonglong2* Wb1 = reinterpret_cast<ulonglong2*>(smem + 196608);

    const int tid = threadIdx.x;
    const int p0  = blockIdx.x * TILE_P;

    // ---- DFT tables ----
    for (int idx = tid; idx < MRI * TD; idx += NTHR) {      // F2[mri][t]
        int mri = idx >> 6, t = idx & 63, m = mri >> 1;
        float s, c;
        sincosf((float)((m * t) & 63) * TWO_PI_OVER_64, &s, &c);
        float v = (mri & 1) ? -s : c;
        F2[idx] = pack2(v, v);
    }
    for (int idx = tid; idx < TD * MRI; idx += NTHR) {      // G2[t][mri]
        int t = idx >> 5, mri = idx & 31, m = mri >> 1;
        float s, c;
        sincosf((float)((m * t) & 63) * TWO_PI_OVER_64, &s, &c);
        float alpha = ((m == 0) ? 1.0f : 2.0f) * (1.0f / 64.0f);
        float v = (mri & 1) ? (-alpha * s) : (alpha * c);
        G2[idx] = pack2(v, v);
    }

    // ---- prefetch W for mode 0 (overlaps with stage 1 gmem reads) ----
    ulonglong2 wreg[4];
#pragma unroll
    for (int k = 0; k < 4; k++) wreg[k] = g_W[tid + k * NTHR];

    __syncthreads();   // tables ready

    // =============== Stage 1: truncated rfft into smem ===============
    // 512 thr = 8 pixels x 2 mri-halves x 32 channel-pairs
    {
        const int cp   = tid & 31;
        const int p    = (tid >> 5) & 7;        // warp-uniform
        const int mri0 = (tid >> 8) << 4;       // 0 or 16, warp-uniform
        const u64* xp = reinterpret_cast<const u64*>(x) + (long)(p0 + p) * 32 + cp;

        u64 acc[16];
#pragma unroll
        for (int i = 0; i < 16; i++) acc[i] = 0ull;

#pragma unroll 4
        for (int t = 0; t < TD; t += 2) {
            u64 xv0 = xp[(long)t * (SCOL / 2)];
            u64 xv1 = xp[(long)(t + 1) * (SCOL / 2)];
#pragma unroll
            for (int i = 0; i < 16; i++) {
                ulonglong2 f = *reinterpret_cast<const ulonglong2*>(&F2[((mri0 + i) << 6) + t]);
                fma2(acc[i], xv0, f.x);
                fma2(acc[i], xv1, f.y);
            }
        }
        u64* Xs64 = reinterpret_cast<u64*>(Xsm);
#pragma unroll
        for (int i = 0; i < 16; i++)
            Xs64[((mri0 + i) * TILE_P + p) * 32 + cp] = acc[i];
        // published at the sync inside the first mode iteration
    }

    // =============== Stage 2: per-mode complex channel mix ===============
    // 512 thr = 8 pixels x 64 outputs; 1 pixel per thread
    {
        const int o  = tid & 63;
        const int px = tid >> 6;                 // 0..7, warp-uniform
        const u64* Xs64 = reinterpret_cast<const u64*>(Xsm);

        for (int m = 0; m < MODES; m++) {
            ulonglong2* Wc = (m & 1) ? Wb1 : Wb0;
#pragma unroll
            for (int k = 0; k < 4; k++) Wc[tid + k * NTHR] = wreg[k];
            __syncthreads();   // W visible; iter 0 also publishes Xsm

            if (m < MODES - 1) {
#pragma unroll
                for (int k = 0; k < 4; k++)
                    wreg[k] = g_W[(m + 1) * 2048 + tid + k * NTHR];
            }

            const u64* xR = Xs64 + ((2 * m)     * TILE_P + px) * 32;
            const u64* xI = Xs64 + ((2 * m + 1) * TILE_P + px) * 32;

            u64 aRR = 0, aII = 0, aRI = 0, aIR = 0;

#pragma unroll 8
            for (int c2 = 0; c2 < 32; c2 += 2) {
                ulonglong2 wv0 = Wc[(c2 << 6) + o];          // LDS.128
                ulonglong2 wv1 = Wc[((c2 + 1) << 6) + o];    // LDS.128
                ulonglong2 xr  = *reinterpret_cast<const ulonglong2*>(&xR[c2]);  // broadcast
                ulonglong2 xi  = *reinterpret_cast<const ulonglong2*>(&xI[c2]);  // broadcast

                fma2(aRR, xr.x, wv0.x); fma2(aII, xi.x, wv0.y);
                fma2(aRI, xr.x, wv0.y); fma2(aIR, xi.x, wv0.x);
                fma2(aRR, xr.y, wv1.x); fma2(aII, xi.y, wv1.y);
                fma2(aRI, xr.y, wv1.y); fma2(aIR, xi.y, wv1.x);
            }

            float yr = hadd(aRR) - hadd(aII);
            float yi = hadd(aRI) + hadd(aIR);
            Ysm[((2 * m)     * TILE_P + px) * 64 + o] = yr;
            Ysm[((2 * m + 1) * TILE_P + px) * 64 + o] = yi;
        }
    }
    __syncthreads();   // Y complete

    // =============== Stage 3: truncated irfft from smem ===============
    // 512 thr = 8 pixels x 2 t-halves x 32 output-pairs
    {
        const int op  = tid & 31;
        const int p   = (tid >> 5) & 7;
        const int t0  = (tid >> 8) << 5;         // 0 or 32
        const u64* Ys64 = reinterpret_cast<const u64*>(Ysm);

        u64 y2[MRI];
#pragma unroll
        for (int mri = 0; mri < MRI; mri++)
            y2[mri] = Ys64[(mri * TILE_P + p) * 32 + op];

        u64* outp = reinterpret_cast<u64*>(out) + (long)(p0 + p) * 32 + op;
#pragma unroll 4
        for (int tt = 0; tt < 32; tt++) {
            const int t = t0 + tt;
            u64 a0 = 0, a1 = 0, a2 = 0, a3 = 0;   // 4 independent chains
#pragma unroll
            for (int q = 0; q < 4; q++) {
                ulonglong2 gA = *reinterpret_cast<const ulonglong2*>(&G2[(t << 5) + 8 * q]);
                ulonglong2 gB = *reinterpret_cast<const ulonglong2*>(&G2[(t << 5) + 8 * q + 2]);
                ulonglong2 gC = *reinterpret_cast<const ulonglong2*>(&G2[(t << 5) + 8 * q + 4]);
                ulonglong2 gD = *reinterpret_cast<const ulonglong2*>(&G2[(t << 5) + 8 * q + 6]);
                fma2(a0, y2[8 * q],     gA.x);
                fma2(a0, y2[8 * q + 1], gA.y);
                fma2(a1, y2[8 * q + 2], gB.x);
                fma2(a1, y2[8 * q + 3], gB.y);
                fma2(a2, y2[8 * q + 4], gC.x);
                fma2(a2, y2[8 * q + 5], gC.y);
                fma2(a3, y2[8 * q + 6], gD.x);
                fma2(a3, y2[8 * q + 7], gD.y);
            }
            outp[(long)t * (SCOL / 2)] = add2(add2(a0, a1), add2(a2, a3));
        }
    }
}

// =====================================================================
extern "C" void kernel_launch(void* const* d_in, const int* in_sizes, int n_in,
                              void* d_out, int out_size) {
    const float* x = (const float*)d_in[0];   // [64][1024][16][64] f32
    const float* w = (const float*)d_in[1];   // [64][64][16][2] f32
    float* out     = (float*)d_out;           // [64][1024][16][64] f32
    (void)in_sizes; (void)n_in; (void)out_size;

    cudaFuncSetAttribute(fused_spectral, cudaFuncAttributeMaxDynamicSharedMemorySize, 229376);

    w_pack<<<128, 256>>>(w);
    fused_spectral<<<NBLK, NTHR, 229376>>>(x, out);
}

// round 7
// speedup vs baseline: 1.2338x; 1.2338x over previous
#include <cuda_runtime.h>

// Problem constants
#define TD     64
#define MODES  16
#define MRI    32          // 2*MODES
#define PD     16384       // N*D pixels
#define SCOL   1048576     // PD*64 floats per time row
#define TILE_P 16
#define NBLK   (PD / TILE_P)   // 1024 CTAs
#define NTHR   256

#define TWO_PI_OVER_64 0.09817477042468103870f

typedef unsigned long long u64;

// Packed, transposed weights: g_W[m][c2][o] = ( (WR[2c2],WR[2c2+1]), (WI[2c2],WI[2c2+1]) )
__device__ ulonglong2 g_W[MODES * 32 * 64];   // 512 KB

// ---------- packed f32x2 helpers ----------
__device__ __forceinline__ u64 pack2(float a, float b) {
    u64 r;
    asm("mov.b64 %0, {%1, %2};" : "=l"(r) : "f"(a), "f"(b));
    return r;
}
__device__ __forceinline__ void unpack2(u64 v, float &lo, float &hi) {
    asm("mov.b64 {%0, %1}, %2;" : "=f"(lo), "=f"(hi) : "l"(v));
}
__device__ __forceinline__ void fma2(u64 &d, u64 a, u64 b) {
    asm("fma.rn.f32x2 %0, %1, %2, %0;" : "+l"(d) : "l"(a), "l"(b));
}
__device__ __forceinline__ u64 add2(u64 a, u64 b) {
    u64 r;
    asm("add.rn.f32x2 %0, %1, %2;" : "=l"(r) : "l"(a), "l"(b));
    return r;
}
__device__ __forceinline__ float hadd(u64 v) {
    float lo, hi;
    unpack2(v, lo, hi);
    return lo + hi;
}

// =====================================================================
// One-time weight repack: w[c][o][m][2]  ->  g_W[m][c2][o]
// =====================================================================
__global__ void __launch_bounds__(256) w_pack(const float* __restrict__ w) {
    int idx = blockIdx.x * 256 + threadIdx.x;     // 0 .. 32767
    int m  = idx >> 11;
    int c2 = (idx >> 6) & 31;
    int o  = idx & 63;
    int c0 = 2 * c2;
    const float* b0 = w + ((((c0    ) * 64 + o) * MODES + m) << 1);
    const float* b1 = w + ((((c0 + 1) * 64 + o) * MODES + m) << 1);
    ulonglong2 v;
    v.x = pack2(b0[0], b1[0]);
    v.y = pack2(b0[1], b1[1]);
    g_W[idx] = v;
}

// =====================================================================
// Fused spectral conv. 256 threads, 16 pixels per CTA, 224 KB smem.
// smem layout (bytes):
//   [0      , 16384 ) F2  [mri][t]   packed (f,f)
//   [16384  , 32768 ) G2  [t][mri]   packed (g,g)
//   [32768  ,163840 ) XY  [mri][16p][64c] f32  (128 KB) — X, overwritten
//                     in-place per mode by Y (mode m owns rows 2m,2m+1)
//   [163840 ,196608 ) W buf 0  [c2][o] ulonglong2
//   [196608 ,229376 ) W buf 1
// =====================================================================
__global__ void __launch_bounds__(NTHR, 1) fused_spectral(const float* __restrict__ x,
                                                          float* __restrict__ out) {
    extern __shared__ __align__(16) char smem[];
    u64*        F2   = reinterpret_cast<u64*>(smem);
    u64*        G2   = reinterpret_cast<u64*>(smem + 16384);
    u64*        XY64 = reinterpret_cast<u64*>(smem + 32768);
    float*      XYf  = reinterpret_cast<float*>(smem + 32768);
    ulonglong2* Wb0  = reinterpret_cast<ulonglong2*>(smem + 163840);
    ulonglong2* Wb1  = reinterpret_cast<ulonglong2*>(smem + 196608);

    const int tid = threadIdx.x;
    const int p0  = blockIdx.x * TILE_P;

    // ---- DFT tables ----
    for (int idx = tid; idx < MRI * TD; idx += NTHR) {      // F2[mri][t]
        int mri = idx >> 6, t = idx & 63, m = mri >> 1;
        float s, c;
        sincosf((float)((m * t) & 63) * TWO_PI_OVER_64, &s, &c);
        float v = (mri & 1) ? -s : c;
        F2[idx] = pack2(v, v);
    }
    for (int idx = tid; idx < TD * MRI; idx += NTHR) {      // G2[t][mri]
        int t = idx >> 5, mri = idx & 31, m = mri >> 1;
        float s, c;
        sincosf((float)((m * t) & 63) * TWO_PI_OVER_64, &s, &c);
        float alpha = ((m == 0) ? 1.0f : 2.0f) * (1.0f / 64.0f);
        float v = (mri & 1) ? (-alpha * s) : (alpha * c);
        G2[idx] = pack2(v, v);
    }

    // ---- prefetch W for mode 0 (overlaps with stage 1 gmem reads) ----
    ulonglong2 wreg[8];
#pragma unroll
    for (int k = 0; k < 8; k++) wreg[k] = g_W[tid + k * NTHR];

    __syncthreads();   // tables ready

    // =============== Stage 1: truncated rfft into smem ===============
    // 256 thr = 8 pixel-slots x 32 channel-pairs; 2 pixel passes.
    {
        const int cp = tid & 31;
        const int pp = tid >> 5;           // 0..7, warp-uniform

#pragma unroll
        for (int pass = 0; pass < 2; pass++) {
            const int p = pp + pass * 8;
            const u64* xp = reinterpret_cast<const u64*>(x) + (long)(p0 + p) * 32 + cp;

            u64 acc[MRI];
#pragma unroll
            for (int i = 0; i < MRI; i++) acc[i] = 0ull;

#pragma unroll 2
            for (int t = 0; t < TD; t += 2) {
                u64 xv0 = xp[(long)t * (SCOL / 2)];
                u64 xv1 = xp[(long)(t + 1) * (SCOL / 2)];
#pragma unroll
                for (int mri = 0; mri < MRI; mri++) {
                    ulonglong2 f = *reinterpret_cast<const ulonglong2*>(&F2[(mri << 6) + t]);
                    fma2(acc[mri], xv0, f.x);
                    fma2(acc[mri], xv1, f.y);
                }
            }
#pragma unroll
            for (int mri = 0; mri < MRI; mri++)
                XY64[(mri * TILE_P + p) * 32 + cp] = acc[mri];
        }
        // published at the first syncthreads inside the mode loop
    }

    // =============== Stage 2: per-mode complex channel mix ===============
    // 256 thr = 4 pixel-groups x 64 outputs; 4 pixels per thread.
    // In-place: mode m reads X rows 2m,2m+1 then overwrites them with Y.
    {
        const int o   = tid & 63;
        const int px0 = (tid >> 6) * 4;           // 0,4,8,12 warp-uniform

        for (int m = 0; m < MODES; m++) {
            ulonglong2* Wc = (m & 1) ? Wb1 : Wb0;
#pragma unroll
            for (int k = 0; k < 8; k++) Wc[tid + k * NTHR] = wreg[k];
            __syncthreads();   // W_m visible; also publishes Xsm (m=0) / Y_{m-1}

            if (m < MODES - 1) {
#pragma unroll
                for (int k = 0; k < 8; k++)
                    wreg[k] = g_W[(m + 1) * 2048 + tid + k * NTHR];
            }

            const u64* xR = XY64 + ((2 * m)     * TILE_P + px0) * 32;
            const u64* xI = XY64 + ((2 * m + 1) * TILE_P + px0) * 32;

            u64 aRR[4], aII[4], aRI[4], aIR[4];
#pragma unroll
            for (int q = 0; q < 4; q++) { aRR[q] = 0; aII[q] = 0; aRI[q] = 0; aIR[q] = 0; }

#pragma unroll 4
            for (int c2 = 0; c2 < 32; c2 += 2) {
                ulonglong2 wv0 = Wc[(c2 << 6) + o];          // LDS.128, conflict-free
                ulonglong2 wv1 = Wc[((c2 + 1) << 6) + o];    // LDS.128, conflict-free
#pragma unroll
                for (int q = 0; q < 4; q++) {
                    ulonglong2 xr = *reinterpret_cast<const ulonglong2*>(&xR[q * 32 + c2]); // bcast
                    ulonglong2 xi = *reinterpret_cast<const ulonglong2*>(&xI[q * 32 + c2]); // bcast
                    fma2(aRR[q], xr.x, wv0.x); fma2(aII[q], xi.x, wv0.y);
                    fma2(aRI[q], xr.x, wv0.y); fma2(aIR[q], xi.x, wv0.x);
                    fma2(aRR[q], xr.y, wv1.x); fma2(aII[q], xi.y, wv1.y);
                    fma2(aRI[q], xr.y, wv1.y); fma2(aIR[q], xi.y, wv1.x);
                }
            }

            __syncthreads();   // all reads of X_m complete before overwrite

#pragma unroll
            for (int q = 0; q < 4; q++) {
                float yr = hadd(aRR[q]) - hadd(aII[q]);
                float yi = hadd(aRI[q]) + hadd(aIR[q]);
                XYf[((2 * m)     * TILE_P + px0 + q) * 64 + o] = yr;
                XYf[((2 * m + 1) * TILE_P + px0 + q) * 64 + o] = yi;
            }
        }
    }
    __syncthreads();   // Y complete

    // =============== Stage 3: truncated irfft from smem ===============
    // 256 thr = 8 pixel-slots x 32 output-pairs; 2 pixel passes.
    {
        const int op = tid & 31;
        const int pp = tid >> 5;

#pragma unroll
        for (int pass = 0; pass < 2; pass++) {
            const int p = pp + pass * 8;

            u64 y2[MRI];
#pragma unroll
            for (int mri = 0; mri < MRI; mri++)
                y2[mri] = XY64[(mri * TILE_P + p) * 32 + op];

            u64* outp = reinterpret_cast<u64*>(out) + (long)(p0 + p) * 32 + op;
#pragma unroll 2
            for (int t = 0; t < TD; t++) {
                u64 a0 = 0, a1 = 0, a2 = 0, a3 = 0;   // 4 independent chains
#pragma unroll
                for (int q = 0; q < 4; q++) {
                    ulonglong2 gA = *reinterpret_cast<const ulonglong2*>(&G2[(t << 5) + 8 * q]);
                    ulonglong2 gB = *reinterpret_cast<const ulonglong2*>(&G2[(t << 5) + 8 * q + 2]);
                    ulonglong2 gC = *reinterpret_cast<const ulonglong2*>(&G2[(t << 5) + 8 * q + 4]);
                    ulonglong2 gD = *reinterpret_cast<const ulonglong2*>(&G2[(t << 5) + 8 * q + 6]);
                    fma2(a0, y2[8 * q],     gA.x);
                    fma2(a0, y2[8 * q + 1], gA.y);
                    fma2(a1, y2[8 * q + 2], gB.x);
                    fma2(a1, y2[8 * q + 3], gB.y);
                    fma2(a2, y2[8 * q + 4], gC.x);
                    fma2(a2, y2[8 * q + 5], gC.y);
                    fma2(a3, y2[8 * q + 6], gD.x);
                    fma2(a3, y2[8 * q + 7], gD.y);
                }
                outp[(long)t * (SCOL / 2)] = add2(add2(a0, a1), add2(a2, a3));
            }
        }
    }
}

// =====================================================================
extern "C" void kernel_launch(void* const* d_in, const int* in_sizes, int n_in,
                              void* d_out, int out_size) {
    const float* x = (const float*)d_in[0];   // [64][1024][16][64] f32
    const float* w = (const float*)d_in[1];   // [64][64][16][2] f32
    float* out     = (float*)d_out;           // [64][1024][16][64] f32
    (void)in_sizes; (void)n_in; (void)out_size;

    cudaFuncSetAttribute(fused_spectral, cudaFuncAttributeMaxDynamicSharedMemorySize, 229376);

    w_pack<<<128, 256>>>(w);
    fused_spectral<<<NBLK, NTHR, 229376>>>(x, out);
}